// round 14
// baseline (speedup 1.0000x reference)
#include <cuda_runtime.h>
#include <cstdint>

// AttnSageGCN: B=32768 nodes, K=32 neighbors, D=128, HIDDEN=128 (4x32), H2=256
#define B_NODES 32768
#define SCALE_ATTN 0.17677669529663687f

typedef unsigned long long ull;

// Scratch (device globals; no runtime allocation allowed)
// g_m layout: per node 528 floats, element (h,j) at h*132 + j (conflict-free banks)
__device__ float g_self[(size_t)B_NODES * 128];
__device__ float g_z[(size_t)B_NODES * 512];    // per node, [h][d] (SCALE folded in)
__device__ float g_m[(size_t)B_NODES * 528];    // per node, [h*132 + j]

// ---------------- packed f32x2 helpers (FFMA2) ----------------
__device__ __forceinline__ ull pack2(float lo, float hi) {
    ull r; asm("mov.b64 %0, {%1, %2};" : "=l"(r) : "f"(lo), "f"(hi)); return r;
}
__device__ __forceinline__ float2 unpack2(ull v) {
    float2 f; asm("mov.b64 {%0, %1}, %2;" : "=f"(f.x), "=f"(f.y) : "l"(v)); return f;
}
__device__ __forceinline__ void fma2(ull& d, ull a, ull b) {
    asm("fma.rn.f32x2 %0, %1, %2, %0;" : "+l"(d) : "l"(a), "l"(b));
}

// ---------------- cp.async helpers (base-target, sm_80+) ----------------
__device__ __forceinline__ uint32_t smem_u32(const void* p) {
    uint32_t a;
    asm("{ .reg .u64 t; cvta.to.shared.u64 t, %1; cvt.u32.u64 %0, t; }" : "=r"(a) : "l"(p));
    return a;
}
__device__ __forceinline__ void cp16(uint32_t dst, const void* src) {
    asm volatile("cp.async.cg.shared.global [%0], [%1], 16;" :: "r"(dst), "l"(src) : "memory");
}
#define CP_COMMIT() asm volatile("cp.async.commit_group;" ::: "memory")
#define CP_WAIT0()  asm volatile("cp.async.wait_group 0;" ::: "memory")
#define CP_WAIT1()  asm volatile("cp.async.wait_group 1;" ::: "memory")

// =====================================================================
// Kernel 1Z (persistent, fused): q = src@wq + bq (SMEM only);
//   self = src@w_self -> g_self;  z[b][h][d] = SCALE * q_h . Wk[d]_h -> g_z
// =====================================================================
#define ZT_STR 132
#define K1Z_XQ 49920
#define K1Z_SMEMF 54144     // 216576 bytes

__global__ void __launch_bounds__(256, 1) k1z(
    const float* __restrict__ src, const float* __restrict__ wq,
    const float* __restrict__ bq, const float* __restrict__ wself,
    const float* __restrict__ wkv)
{
    extern __shared__ float s1[];
    float* W  = s1;              // [128][256]
    float* bb = s1 + 32768;      // [256]
    float* WT = s1 + 33024;      // [128 cols][132]: WT[c][d] = wkv[d][c]
    float* xq = s1 + K1Z_XQ;     // overlay: xs[32][128] then qs[32][132]
    int t = threadIdx.x;

    for (int i = t; i < 16384; i += 256) {
        int d = i >> 7, j = i & 127;
        W[d * 256 + j]       = wq[i];
        W[d * 256 + 128 + j] = wself[i];
    }
    if (t < 128) { bb[t] = bq[t]; bb[128 + t] = 0.f; }
    {   // Wk transpose (cols 0..127 of wkv)
        int d = t >> 1, c0 = (t & 1) * 64;
#pragma unroll
        for (int i = 0; i < 16; i++) {
            float4 v = *(const float4*)&wkv[d * 256 + c0 + i * 4];
            WT[(c0 + i * 4 + 0) * ZT_STR + d] = v.x;
            WT[(c0 + i * 4 + 1) * ZT_STR + d] = v.y;
            WT[(c0 + i * 4 + 2) * ZT_STR + d] = v.z;
            WT[(c0 + i * 4 + 3) * ZT_STR + d] = v.w;
        }
    }
    int c = blockIdx.x;
    if (c < 1024) {
        size_t r0 = (size_t)c * 4096;
        for (int i = t * 4; i < 4096; i += 1024)
            *(float4*)&xq[i] = *(const float4*)&src[r0 + i];
    }
    __syncthreads();

    int tj = t & 63, tk = t >> 6;
    int jb = tj * 4, rb = tk * 8;
    int hd0 = (t & 63) * 8;
    int zh = hd0 >> 7, zd0 = hd0 & 127;
    int zg0 = (t >> 6) * 8;

    while (c < 1024) {
        int cn = c + gridDim.x;
        float4 pfr[4];
        if (cn < 1024) {
            const float4* s4 = (const float4*)&src[(size_t)cn * 4096 + t * 16];
#pragma unroll
            for (int i = 0; i < 4; i++) pfr[i] = s4[i];
        }
        // ---- q/self GEMM (xq as xs, stride 128) ----
        float4 bj = *(float4*)&bb[jb];
        ull acc[8][2];
#pragma unroll
        for (int i = 0; i < 8; i++) {
            acc[i][0] = pack2(bj.x, bj.y);
            acc[i][1] = pack2(bj.z, bj.w);
        }
#pragma unroll 4
        for (int d = 0; d < 128; d += 2) {
            ulonglong2 w0 = *(ulonglong2*)&W[d * 256 + jb];
            ulonglong2 w1 = *(ulonglong2*)&W[(d + 1) * 256 + jb];
#pragma unroll
            for (int i = 0; i < 8; i++) {
                float2 av = *(float2*)&xq[(rb + i) * 128 + d];
                ull a0 = pack2(av.x, av.x), a1 = pack2(av.y, av.y);
                fma2(acc[i][0], a0, w0.x); fma2(acc[i][1], a0, w0.y);
                fma2(acc[i][0], a1, w1.x); fma2(acc[i][1], a1, w1.y);
            }
        }
        __syncthreads();   // everyone done reading xs
        size_t row0 = (size_t)c * 32;
#pragma unroll
        for (int i = 0; i < 8; i++) {
            float2 u = unpack2(acc[i][0]), v = unpack2(acc[i][1]);
            float4 o = make_float4(u.x, u.y, v.x, v.y);
            if (jb < 128) *(float4*)&xq[(rb + i) * ZT_STR + jb] = o;         // q -> SMEM
            else *(float4*)&g_self[(row0 + rb + i) * 128 + (jb - 128)] = o;  // self -> HBM
        }
        __syncthreads();   // qs ready

        // ---- z phase (xq as qs, stride 132) ----
        ull zacc[8][4];
#pragma unroll
        for (int gg = 0; gg < 8; gg++)
#pragma unroll
            for (int i = 0; i < 4; i++) zacc[gg][i] = 0ULL;
#pragma unroll 4
        for (int j = 0; j < 32; j++) {
            const float* wr = &WT[(32 * zh + j) * ZT_STR + zd0];
            ulonglong2 w0 = *(const ulonglong2*)wr;
            ulonglong2 w1 = *(const ulonglong2*)(wr + 4);
#pragma unroll
            for (int gg = 0; gg < 8; gg++) {
                float qv = xq[(zg0 + gg) * ZT_STR + 32 * zh + j];
                ull qp = pack2(qv, qv);
                fma2(zacc[gg][0], qp, w0.x); fma2(zacc[gg][1], qp, w0.y);
                fma2(zacc[gg][2], qp, w1.x); fma2(zacc[gg][3], qp, w1.y);
            }
        }
#pragma unroll
        for (int gg = 0; gg < 8; gg++) {
            float2 a = unpack2(zacc[gg][0]), b = unpack2(zacc[gg][1]);
            float2 cc = unpack2(zacc[gg][2]), dd = unpack2(zacc[gg][3]);
            size_t base = (row0 + zg0 + gg) * 512 + hd0;
            *(float4*)&g_z[base] = make_float4(a.x * SCALE_ATTN, a.y * SCALE_ATTN,
                                               b.x * SCALE_ATTN, b.y * SCALE_ATTN);
            *(float4*)&g_z[base + 4] = make_float4(cc.x * SCALE_ATTN, cc.y * SCALE_ATTN,
                                                   dd.x * SCALE_ATTN, dd.y * SCALE_ATTN);
        }
        __syncthreads();   // everyone done reading qs
        if (cn < 1024) {
#pragma unroll
            for (int i = 0; i < 4; i++) *(float4*)&xq[t * 16 + i * 4] = pfr[i];
        }
        __syncthreads();
        c = cn;
    }
}

// =====================================================================
// Kernel 2: streaming attention, warp-per-node, 8 warps, RING-OF-3
// half-buffers per warp (proven R12 structure).
// =====================================================================
#define NB_HALF 2112                     // 16 rows x 132
#define K2_OFF_ZB 50688                  // 8 warps x 3 x 2112
#define K2_OFF_PB 54784                  // + 8 x 512
#define K2_SMEMF 56832                   // 227328 bytes

__device__ __forceinline__ void k2_half(uint32_t dst_a, const float* __restrict__ src,
                                        int lane) {
#pragma unroll
    for (int i = 0; i < 16; i++)
        cp16(dst_a + i * 528 + lane * 16, src + i * 128 + lane * 4);
}

__global__ void __launch_bounds__(256, 1) k2_attn(const float* __restrict__ nbr)
{
    extern __shared__ float s2[];
    uint32_t sb = smem_u32(s2);
    int t = threadIdx.x, w = t >> 5, lane = t & 31;
    float* HB = s2 + w * 3 * NB_HALF;
    float* zb = s2 + K2_OFF_ZB + w * 512;
    float* pb = s2 + K2_OFF_PB + w * 256;
    uint32_t HBa = sb + (w * 3 * NB_HALF) * 4;
    uint32_t zba = sb + (K2_OFF_ZB + w * 512) * 4;

    int node = blockIdx.x * 8 + w;
    const int stride = gridDim.x * 8;
    int it3 = 0;

    if (node < B_NODES) {   // prologue: node0 full (slots 0,1) + z; node1 first (slot 2)
        const float* ns = nbr + (size_t)node * 4096;
        k2_half(HBa, ns, lane);
        k2_half(HBa + NB_HALF * 4, ns + 16 * 128, lane);
        const float* zsrc = g_z + (size_t)node * 512 + lane * 16;
#pragma unroll
        for (int i = 0; i < 4; i++) cp16(zba + lane * 64 + i * 16, zsrc + i * 4);
        CP_COMMIT();
        int n1 = node + stride;
        if (n1 < B_NODES) {
            k2_half(HBa + 2 * NB_HALF * 4, nbr + (size_t)n1 * 4096, lane);
            CP_COMMIT();
        }
    }

    while (node < B_NODES) {
        int nxt = node + stride;
        int nxt2 = node + 2 * stride;
        if (nxt < B_NODES) CP_WAIT1(); else CP_WAIT0();
        __syncwarp();
        int sF = (it3 == 0) ? 0 : (it3 == 1 ? 2 : 1);
        int sS = (it3 == 0) ? 1 : (it3 == 1 ? 0 : 2);
        const float* nbF = HB + sF * NB_HALF;
        const float* nbS = HB + sS * NB_HALF;

        // ---- logits: lane = neighbor k ----
        const float* row = (lane < 16) ? (nbF + lane * 132) : (nbS + (lane - 16) * 132);
        ull lga[4], lgb[4];
#pragma unroll
        for (int h = 0; h < 4; h++) { lga[h] = 0ULL; lgb[h] = 0ULL; }
#pragma unroll 4
        for (int d4 = 0; d4 < 32; d4++) {
            ulonglong2 nv = *(const ulonglong2*)(row + d4 * 4);
#pragma unroll
            for (int h = 0; h < 4; h++) {
                ulonglong2 zv = *(const ulonglong2*)(zb + h * 128 + d4 * 4);
                fma2(lga[h], nv.x, zv.x);
                fma2(lgb[h], nv.y, zv.y);
            }
        }
        float p[4];
#pragma unroll
        for (int h = 0; h < 4; h++) {
            float2 a = unpack2(lga[h]), b = unpack2(lgb[h]);
            float lg = (a.x + a.y) + (b.x + b.y);
            float mx = lg;
#pragma unroll
            for (int o = 16; o > 0; o >>= 1)
                mx = fmaxf(mx, __shfl_xor_sync(0xffffffffu, mx, o));
            float e = __expf(lg - mx);
            float sum = e;
#pragma unroll
            for (int o = 16; o > 0; o >>= 1)
                sum += __shfl_xor_sync(0xffffffffu, sum, o);
            p[h] = e / sum;
        }
        *(float4*)&pb[lane * 8]     = make_float4(p[0], p[0], p[1], p[1]);
        *(float4*)&pb[lane * 8 + 4] = make_float4(p[2], p[2], p[3], p[3]);
        __syncwarp();

        if (nxt < B_NODES) {          // G1: z(next)
            const float* zsrc = g_z + (size_t)nxt * 512 + lane * 16;
#pragma unroll
            for (int i = 0; i < 4; i++) cp16(zba + lane * 64 + i * 16, zsrc + i * 4);
            CP_COMMIT();
        }

        // ---- m (FFMA2): lane owns d-chunk [4*lane, 4*lane+4) ----
        ull mac[4][2];
#pragma unroll
        for (int h = 0; h < 4; h++) { mac[h][0] = 0ULL; mac[h][1] = 0ULL; }
#pragma unroll 4
        for (int k = 0; k < 16; k++) {
            ulonglong2 pa = *(const ulonglong2*)&pb[k * 8];
            ulonglong2 pc = *(const ulonglong2*)&pb[k * 8 + 4];
            ulonglong2 nv = *(const ulonglong2*)&nbF[k * 132 + 4 * lane];
            fma2(mac[0][0], pa.x, nv.x); fma2(mac[0][1], pa.x, nv.y);
            fma2(mac[1][0], pa.y, nv.x); fma2(mac[1][1], pa.y, nv.y);
            fma2(mac[2][0], pc.x, nv.x); fma2(mac[2][1], pc.x, nv.y);
            fma2(mac[3][0], pc.y, nv.x); fma2(mac[3][1], pc.y, nv.y);
        }
        if (nxt < B_NODES) {          // G2: next SECOND half -> slot sF
            __syncwarp();
            k2_half(HBa + sF * NB_HALF * 4, nbr + (size_t)nxt * 4096 + 16 * 128, lane);
            CP_COMMIT();
        }
#pragma unroll 4
        for (int k = 16; k < 32; k++) {
            ulonglong2 pa = *(const ulonglong2*)&pb[k * 8];
            ulonglong2 pc = *(const ulonglong2*)&pb[k * 8 + 4];
            ulonglong2 nv = *(const ulonglong2*)&nbS[(k - 16) * 132 + 4 * lane];
            fma2(mac[0][0], pa.x, nv.x); fma2(mac[0][1], pa.x, nv.y);
            fma2(mac[1][0], pa.y, nv.x); fma2(mac[1][1], pa.y, nv.y);
            fma2(mac[2][0], pc.x, nv.x); fma2(mac[2][1], pc.x, nv.y);
            fma2(mac[3][0], pc.y, nv.x); fma2(mac[3][1], pc.y, nv.y);
        }
        if (nxt2 < B_NODES) {         // G3: next2 FIRST half -> slot sS
            __syncwarp();
            k2_half(HBa + sS * NB_HALF * 4, nbr + (size_t)nxt2 * 4096, lane);
            CP_COMMIT();
        }

        size_t mb = (size_t)node * 528;
#pragma unroll
        for (int h = 0; h < 4; h++) {
            float2 u = unpack2(mac[h][0]), v = unpack2(mac[h][1]);
            *(float4*)&g_m[mb + h * 132 + 4 * lane] = make_float4(u.x, u.y, v.x, v.y);
        }

        node = nxt;
        it3 = (it3 == 2) ? 0 : it3 + 1;
    }
}

// =====================================================================
// Kernel 34 (fused V + output, persistent, warp-specialized pipeline):
//   stage1 (warps 0-3):  v[16nodes][128] = m@Wv + bv       -> vt[pb]
//   stage2 (warps 4-7):  out = relu(self + vt[pb^1]@wo + bo) (prev tile)
//   m tiles (16 nodes x 528) cp.async double-buffered.
// =====================================================================
#define NT34 2048
#define K34_WV 0          // Wv dense [128][128]
#define K34_WO 16384      // wo dense [128][128]
#define K34_MS 32768      // 2 x 8448
#define K34_VT 49664      // 2 x (16 x 132)
#define K34_BV 53888      // 128
#define K34_BO 54016      // 128
#define K34_SMEMF 54144   // 216576 bytes

__global__ void __launch_bounds__(256, 1) k34(
    const float* __restrict__ wkv, const float* __restrict__ bkv,
    const float* __restrict__ wo, const float* __restrict__ bo,
    float* __restrict__ out)
{
    extern __shared__ float s4[];
    uint32_t sb = smem_u32(s4);
    int t = threadIdx.x, wid = t >> 5;

    for (int i = t * 4; i < 16384; i += 1024) {       // Wv[j][c] = wkv[j][128+c]
        int j = i >> 7, cc = i & 127;
        *(float4*)&s4[K34_WV + i] = *(const float4*)&wkv[j * 256 + 128 + cc];
    }
    for (int i = t * 4; i < 16384; i += 1024)
        *(float4*)&s4[K34_WO + i] = *(const float4*)&wo[i];
    if (t < 32) *(float4*)&s4[K34_BV + t * 4] = *(const float4*)&bkv[128 + t * 4];
    else if (t < 64) *(float4*)&s4[K34_BO + (t - 32) * 4] = *(const float4*)&bo[(t - 32) * 4];

    const int G = gridDim.x;
    const int cb = blockIdx.x;

    if (cb < NT34) {   // prologue: m[cb] -> buf0
        const float* src = g_m + (size_t)cb * 8448;
        uint32_t dst = sb + K34_MS * 4;
        for (int i = t; i < 2112; i += 256) cp16(dst + i * 16, src + i * 4);
    }
    CP_COMMIT();

    int s1c0 = (t & 31) * 4, s1g0 = (wid & 3) * 4, s1h = s1c0 >> 5;
    int s2jb = (t & 31) * 4, s2rb = (wid & 3) * 4;
    int pb2 = 0, mb2 = 0;

    for (int i = 0;; i++) {
        long c = cb + (long)i * G;
        long cp = c - G;
        bool s1 = (c < NT34);
        bool s2 = (i > 0) && (cp < NT34);
        if (!s1 && !s2) break;
        long cn = c + G;
        if (s1 && cn < NT34) {
            const float* src = g_m + (size_t)cn * 8448;
            uint32_t dst = sb + (K34_MS + (mb2 ^ 1) * 8448) * 4;
            for (int i2 = t; i2 < 2112; i2 += 256) cp16(dst + i2 * 16, src + i2 * 4);
        }
        CP_COMMIT();
        CP_WAIT1();        // m[c]'s group complete (newest may be in flight)
        __syncthreads();   // + weights ready on iter 0; vt[pb^1] from prev iter

        if (s1 && wid < 4) {
            const float* msb = s4 + K34_MS + mb2 * 8448;
            float* vtb = s4 + K34_VT + pb2 * 2112;
            float4 bv4 = *(float4*)&s4[K34_BV + s1c0];
            ull acc[4][2];
#pragma unroll
            for (int gg = 0; gg < 4; gg++) {
                acc[gg][0] = pack2(bv4.x, bv4.y);
                acc[gg][1] = pack2(bv4.z, bv4.w);
            }
#pragma unroll 4
            for (int j4 = 0; j4 < 128; j4 += 4) {
                ulonglong2 w0 = *(ulonglong2*)&s4[K34_WV + (j4 + 0) * 128 + s1c0];
                ulonglong2 w1 = *(ulonglong2*)&s4[K34_WV + (j4 + 1) * 128 + s1c0];
                ulonglong2 w2 = *(ulonglong2*)&s4[K34_WV + (j4 + 2) * 128 + s1c0];
                ulonglong2 w3 = *(ulonglong2*)&s4[K34_WV + (j4 + 3) * 128 + s1c0];
#pragma unroll
                for (int gg = 0; gg < 4; gg++) {
                    float4 mv = *(const float4*)&msb[(s1g0 + gg) * 528 + s1h * 132 + j4];
                    ull m0 = pack2(mv.x, mv.x), m1 = pack2(mv.y, mv.y);
                    ull m2 = pack2(mv.z, mv.z), m3 = pack2(mv.w, mv.w);
                    fma2(acc[gg][0], m0, w0.x); fma2(acc[gg][1], m0, w0.y);
                    fma2(acc[gg][0], m1, w1.x); fma2(acc[gg][1], m1, w1.y);
                    fma2(acc[gg][0], m2, w2.x); fma2(acc[gg][1], m2, w2.y);
                    fma2(acc[gg][0], m3, w3.x); fma2(acc[gg][1], m3, w3.y);
                }
            }
#pragma unroll
            for (int gg = 0; gg < 4; gg++) {
                float2 u = unpack2(acc[gg][0]), v = unpack2(acc[gg][1]);
                *(float4*)&vtb[(s1g0 + gg) * 132 + s1c0] = make_float4(u.x, u.y, v.x, v.y);
            }
        }

        if (s2 && wid >= 4) {
            const float* vtb = s4 + K34_VT + (pb2 ^ 1) * 2112;
            float4 bo4 = *(float4*)&s4[K34_BO + s2jb];
            ull acc[4][2];
#pragma unroll
            for (int rr = 0; rr < 4; rr++) {
                acc[rr][0] = pack2(bo4.x, bo4.y);
                acc[rr][1] = pack2(bo4.z, bo4.w);
            }
#pragma unroll 4
            for (int d = 0; d < 128; d += 2) {
                ulonglong2 w0 = *(ulonglong2*)&s4[K34_WO + d * 128 + s2jb];
                ulonglong2 w1 = *(ulonglong2*)&s4[K34_WO + (d + 1) * 128 + s2jb];
#pragma unroll
                for (int rr = 0; rr < 4; rr++) {
                    float2 vv = *(const float2*)&vtb[(s2rb + rr) * 132 + d];
                    ull a0 = pack2(vv.x, vv.x), a1 = pack2(vv.y, vv.y);
                    fma2(acc[rr][0], a0, w0.x); fma2(acc[rr][1], a0, w0.y);
                    fma2(acc[rr][0], a1, w1.x); fma2(acc[rr][1], a1, w1.y);
                }
            }
            size_t row0 = (size_t)cp * 16;
#pragma unroll
            for (int rr = 0; rr < 4; rr++) {
                size_t r = row0 + s2rb + rr;
                float4 sv = *(const float4*)&g_self[r * 128 + s2jb];
                float2 u = unpack2(acc[rr][0]), v = unpack2(acc[rr][1]);
                float4 o = make_float4(fmaxf(u.x + sv.x, 0.f), fmaxf(u.y + sv.y, 0.f),
                                       fmaxf(v.x + sv.z, 0.f), fmaxf(v.y + sv.w, 0.f));
                *(float4*)&out[r * 128 + s2jb] = o;
            }
        }
        __syncthreads();
        pb2 ^= 1; mb2 ^= 1;
    }
}

// =====================================================================
// Launch
// =====================================================================
#define K1Z_SMEM (K1Z_SMEMF * 4)                                       // 216576
#define K2_SMEM  (K2_SMEMF * 4)                                        // 227328
#define K34_SMEM (K34_SMEMF * 4)                                       // 216576

extern "C" void kernel_launch(void* const* d_in, const int* in_sizes, int n_in,
                              void* d_out, int out_size)
{
    const float* src   = (const float*)d_in[0];
    const float* nbr   = (const float*)d_in[1];
    const float* wq    = (const float*)d_in[2];
    const float* bq    = (const float*)d_in[3];
    const float* wkv   = (const float*)d_in[4];
    const float* bkv   = (const float*)d_in[5];
    const float* wo    = (const float*)d_in[6];
    const float* bo    = (const float*)d_in[7];
    const float* wself = (const float*)d_in[8];
    float* out = (float*)d_out;

    cudaFuncSetAttribute(k1z,     cudaFuncAttributeMaxDynamicSharedMemorySize, K1Z_SMEM);
    cudaFuncSetAttribute(k2_attn, cudaFuncAttributeMaxDynamicSharedMemorySize, K2_SMEM);
    cudaFuncSetAttribute(k34,     cudaFuncAttributeMaxDynamicSharedMemorySize, K34_SMEM);

    int dev = 0;
    cudaGetDevice(&dev);
    int nsm = 148;
    cudaDeviceGetAttribute(&nsm, cudaDevAttrMultiProcessorCount, dev);

    k1z<<<nsm, 256, K1Z_SMEM>>>(src, wq, bq, wself, wkv);
    k2_attn<<<nsm, 256, K2_SMEM>>>(nbr);
    k34<<<nsm, 256, K34_SMEM>>>(wkv, bkv, wo, bo, out);
}

// round 15
// speedup vs baseline: 1.0438x; 1.0438x over previous
#include <cuda_runtime.h>
#include <cstdint>

// AttnSageGCN: B=32768 nodes, K=32 neighbors, D=128, HIDDEN=128 (4x32), H2=256
#define B_NODES 32768
#define SCALE_ATTN 0.17677669529663687f

typedef unsigned long long ull;

// Scratch (device globals; no runtime allocation allowed)
// g_m layout: per node 528 floats, element (h,j) at h*132 + j (conflict-free banks)
__device__ float g_self[(size_t)B_NODES * 128];
__device__ float g_z[(size_t)B_NODES * 512];    // per node, [h][d] (SCALE folded in)
__device__ float g_m[(size_t)B_NODES * 528];    // per node, [h*132 + j]

// ---------------- packed f32x2 helpers (FFMA2) ----------------
__device__ __forceinline__ ull pack2(float lo, float hi) {
    ull r; asm("mov.b64 %0, {%1, %2};" : "=l"(r) : "f"(lo), "f"(hi)); return r;
}
__device__ __forceinline__ float2 unpack2(ull v) {
    float2 f; asm("mov.b64 {%0, %1}, %2;" : "=f"(f.x), "=f"(f.y) : "l"(v)); return f;
}
__device__ __forceinline__ void fma2(ull& d, ull a, ull b) {
    asm("fma.rn.f32x2 %0, %1, %2, %0;" : "+l"(d) : "l"(a), "l"(b));
}

// ---------------- cp.async helpers (base-target, sm_80+) ----------------
__device__ __forceinline__ uint32_t smem_u32(const void* p) {
    uint32_t a;
    asm("{ .reg .u64 t; cvta.to.shared.u64 t, %1; cvt.u32.u64 %0, t; }" : "=r"(a) : "l"(p));
    return a;
}
__device__ __forceinline__ void cp16(uint32_t dst, const void* src) {
    asm volatile("cp.async.cg.shared.global [%0], [%1], 16;" :: "r"(dst), "l"(src) : "memory");
}
#define CP_COMMIT() asm volatile("cp.async.commit_group;" ::: "memory")
#define CP_WAIT0()  asm volatile("cp.async.wait_group 0;" ::: "memory")
#define CP_WAIT1()  asm volatile("cp.async.wait_group 1;" ::: "memory")

// =====================================================================
// Kernel 1Z (persistent, fused): q = src@wq + bq (SMEM only);
//   self = src@w_self -> g_self;  z[b][h][d] = SCALE * q_h . Wk[d]_h -> g_z
// =====================================================================
#define ZT_STR 132
#define K1Z_XQ 49920
#define K1Z_SMEMF 54144     // 216576 bytes

__global__ void __launch_bounds__(256, 1) k1z(
    const float* __restrict__ src, const float* __restrict__ wq,
    const float* __restrict__ bq, const float* __restrict__ wself,
    const float* __restrict__ wkv)
{
    extern __shared__ float s1[];
    float* W  = s1;              // [128][256]
    float* bb = s1 + 32768;      // [256]
    float* WT = s1 + 33024;      // [128 cols][132]: WT[c][d] = wkv[d][c]
    float* xq = s1 + K1Z_XQ;     // overlay: xs[32][128] then qs[32][132]
    int t = threadIdx.x;

    for (int i = t; i < 16384; i += 256) {
        int d = i >> 7, j = i & 127;
        W[d * 256 + j]       = wq[i];
        W[d * 256 + 128 + j] = wself[i];
    }
    if (t < 128) { bb[t] = bq[t]; bb[128 + t] = 0.f; }
    {   // Wk transpose (cols 0..127 of wkv)
        int d = t >> 1, c0 = (t & 1) * 64;
#pragma unroll
        for (int i = 0; i < 16; i++) {
            float4 v = *(const float4*)&wkv[d * 256 + c0 + i * 4];
            WT[(c0 + i * 4 + 0) * ZT_STR + d] = v.x;
            WT[(c0 + i * 4 + 1) * ZT_STR + d] = v.y;
            WT[(c0 + i * 4 + 2) * ZT_STR + d] = v.z;
            WT[(c0 + i * 4 + 3) * ZT_STR + d] = v.w;
        }
    }
    int c = blockIdx.x;
    if (c < 1024) {
        size_t r0 = (size_t)c * 4096;
        for (int i = t * 4; i < 4096; i += 1024)
            *(float4*)&xq[i] = *(const float4*)&src[r0 + i];
    }
    __syncthreads();

    int tj = t & 63, tk = t >> 6;
    int jb = tj * 4, rb = tk * 8;
    int hd0 = (t & 63) * 8;
    int zh = hd0 >> 7, zd0 = hd0 & 127;
    int zg0 = (t >> 6) * 8;

    while (c < 1024) {
        int cn = c + gridDim.x;
        float4 pfr[4];
        if (cn < 1024) {
            const float4* s4 = (const float4*)&src[(size_t)cn * 4096 + t * 16];
#pragma unroll
            for (int i = 0; i < 4; i++) pfr[i] = s4[i];
        }
        // ---- q/self GEMM (xq as xs, stride 128) ----
        float4 bj = *(float4*)&bb[jb];
        ull acc[8][2];
#pragma unroll
        for (int i = 0; i < 8; i++) {
            acc[i][0] = pack2(bj.x, bj.y);
            acc[i][1] = pack2(bj.z, bj.w);
        }
#pragma unroll 4
        for (int d = 0; d < 128; d += 2) {
            ulonglong2 w0 = *(ulonglong2*)&W[d * 256 + jb];
            ulonglong2 w1 = *(ulonglong2*)&W[(d + 1) * 256 + jb];
#pragma unroll
            for (int i = 0; i < 8; i++) {
                float2 av = *(float2*)&xq[(rb + i) * 128 + d];
                ull a0 = pack2(av.x, av.x), a1 = pack2(av.y, av.y);
                fma2(acc[i][0], a0, w0.x); fma2(acc[i][1], a0, w0.y);
                fma2(acc[i][0], a1, w1.x); fma2(acc[i][1], a1, w1.y);
            }
        }
        __syncthreads();   // everyone done reading xs
        size_t row0 = (size_t)c * 32;
#pragma unroll
        for (int i = 0; i < 8; i++) {
            float2 u = unpack2(acc[i][0]), v = unpack2(acc[i][1]);
            float4 o = make_float4(u.x, u.y, v.x, v.y);
            if (jb < 128) *(float4*)&xq[(rb + i) * ZT_STR + jb] = o;         // q -> SMEM
            else *(float4*)&g_self[(row0 + rb + i) * 128 + (jb - 128)] = o;  // self -> HBM
        }
        __syncthreads();   // qs ready

        // ---- z phase (xq as qs, stride 132) ----
        ull zacc[8][4];
#pragma unroll
        for (int gg = 0; gg < 8; gg++)
#pragma unroll
            for (int i = 0; i < 4; i++) zacc[gg][i] = 0ULL;
#pragma unroll 4
        for (int j = 0; j < 32; j++) {
            const float* wr = &WT[(32 * zh + j) * ZT_STR + zd0];
            ulonglong2 w0 = *(const ulonglong2*)wr;
            ulonglong2 w1 = *(const ulonglong2*)(wr + 4);
#pragma unroll
            for (int gg = 0; gg < 8; gg++) {
                float qv = xq[(zg0 + gg) * ZT_STR + 32 * zh + j];
                ull qp = pack2(qv, qv);
                fma2(zacc[gg][0], qp, w0.x); fma2(zacc[gg][1], qp, w0.y);
                fma2(zacc[gg][2], qp, w1.x); fma2(zacc[gg][3], qp, w1.y);
            }
        }
#pragma unroll
        for (int gg = 0; gg < 8; gg++) {
            float2 a = unpack2(zacc[gg][0]), b = unpack2(zacc[gg][1]);
            float2 cc = unpack2(zacc[gg][2]), dd = unpack2(zacc[gg][3]);
            size_t base = (row0 + zg0 + gg) * 512 + hd0;
            *(float4*)&g_z[base] = make_float4(a.x * SCALE_ATTN, a.y * SCALE_ATTN,
                                               b.x * SCALE_ATTN, b.y * SCALE_ATTN);
            *(float4*)&g_z[base + 4] = make_float4(cc.x * SCALE_ATTN, cc.y * SCALE_ATTN,
                                                   dd.x * SCALE_ATTN, dd.y * SCALE_ATTN);
        }
        __syncthreads();   // everyone done reading qs
        if (cn < 1024) {
#pragma unroll
            for (int i = 0; i < 4; i++) *(float4*)&xq[t * 16 + i * 4] = pfr[i];
        }
        __syncthreads();
        c = cn;
    }
}

// =====================================================================
// Kernel 2: streaming attention, warp-per-node, 8 warps, RING-OF-3
// half-buffers per warp (proven R12 structure).
// =====================================================================
#define NB_HALF 2112                     // 16 rows x 132
#define K2_OFF_ZB 50688                  // 8 warps x 3 x 2112
#define K2_OFF_PB 54784                  // + 8 x 512
#define K2_SMEMF 56832                   // 227328 bytes

__device__ __forceinline__ void k2_half(uint32_t dst_a, const float* __restrict__ src,
                                        int lane) {
#pragma unroll
    for (int i = 0; i < 16; i++)
        cp16(dst_a + i * 528 + lane * 16, src + i * 128 + lane * 4);
}

__global__ void __launch_bounds__(256, 1) k2_attn(const float* __restrict__ nbr)
{
    extern __shared__ float s2[];
    uint32_t sb = smem_u32(s2);
    int t = threadIdx.x, w = t >> 5, lane = t & 31;
    float* HB = s2 + w * 3 * NB_HALF;
    float* zb = s2 + K2_OFF_ZB + w * 512;
    float* pb = s2 + K2_OFF_PB + w * 256;
    uint32_t HBa = sb + (w * 3 * NB_HALF) * 4;
    uint32_t zba = sb + (K2_OFF_ZB + w * 512) * 4;

    int node = blockIdx.x * 8 + w;
    const int stride = gridDim.x * 8;
    int it3 = 0;

    if (node < B_NODES) {   // prologue: node0 full (slots 0,1) + z; node1 first (slot 2)
        const float* ns = nbr + (size_t)node * 4096;
        k2_half(HBa, ns, lane);
        k2_half(HBa + NB_HALF * 4, ns + 16 * 128, lane);
        const float* zsrc = g_z + (size_t)node * 512 + lane * 16;
#pragma unroll
        for (int i = 0; i < 4; i++) cp16(zba + lane * 64 + i * 16, zsrc + i * 4);
        CP_COMMIT();
        int n1 = node + stride;
        if (n1 < B_NODES) {
            k2_half(HBa + 2 * NB_HALF * 4, nbr + (size_t)n1 * 4096, lane);
            CP_COMMIT();
        }
    }

    while (node < B_NODES) {
        int nxt = node + stride;
        int nxt2 = node + 2 * stride;
        if (nxt < B_NODES) CP_WAIT1(); else CP_WAIT0();
        __syncwarp();
        int sF = (it3 == 0) ? 0 : (it3 == 1 ? 2 : 1);
        int sS = (it3 == 0) ? 1 : (it3 == 1 ? 0 : 2);
        const float* nbF = HB + sF * NB_HALF;
        const float* nbS = HB + sS * NB_HALF;

        // ---- logits: lane = neighbor k ----
        const float* row = (lane < 16) ? (nbF + lane * 132) : (nbS + (lane - 16) * 132);
        ull lga[4], lgb[4];
#pragma unroll
        for (int h = 0; h < 4; h++) { lga[h] = 0ULL; lgb[h] = 0ULL; }
#pragma unroll 4
        for (int d4 = 0; d4 < 32; d4++) {
            ulonglong2 nv = *(const ulonglong2*)(row + d4 * 4);
#pragma unroll
            for (int h = 0; h < 4; h++) {
                ulonglong2 zv = *(const ulonglong2*)(zb + h * 128 + d4 * 4);
                fma2(lga[h], nv.x, zv.x);
                fma2(lgb[h], nv.y, zv.y);
            }
        }
        float p[4];
#pragma unroll
        for (int h = 0; h < 4; h++) {
            float2 a = unpack2(lga[h]), b = unpack2(lgb[h]);
            float lg = (a.x + a.y) + (b.x + b.y);
            float mx = lg;
#pragma unroll
            for (int o = 16; o > 0; o >>= 1)
                mx = fmaxf(mx, __shfl_xor_sync(0xffffffffu, mx, o));
            float e = __expf(lg - mx);
            float sum = e;
#pragma unroll
            for (int o = 16; o > 0; o >>= 1)
                sum += __shfl_xor_sync(0xffffffffu, sum, o);
            p[h] = e / sum;
        }
        *(float4*)&pb[lane * 8]     = make_float4(p[0], p[0], p[1], p[1]);
        *(float4*)&pb[lane * 8 + 4] = make_float4(p[2], p[2], p[3], p[3]);
        __syncwarp();

        if (nxt < B_NODES) {          // G1: z(next)
            const float* zsrc = g_z + (size_t)nxt * 512 + lane * 16;
#pragma unroll
            for (int i = 0; i < 4; i++) cp16(zba + lane * 64 + i * 16, zsrc + i * 4);
            CP_COMMIT();
        }

        // ---- m (FFMA2): lane owns d-chunk [4*lane, 4*lane+4) ----
        ull mac[4][2];
#pragma unroll
        for (int h = 0; h < 4; h++) { mac[h][0] = 0ULL; mac[h][1] = 0ULL; }
#pragma unroll 4
        for (int k = 0; k < 16; k++) {
            ulonglong2 pa = *(const ulonglong2*)&pb[k * 8];
            ulonglong2 pc = *(const ulonglong2*)&pb[k * 8 + 4];
            ulonglong2 nv = *(const ulonglong2*)&nbF[k * 132 + 4 * lane];
            fma2(mac[0][0], pa.x, nv.x); fma2(mac[0][1], pa.x, nv.y);
            fma2(mac[1][0], pa.y, nv.x); fma2(mac[1][1], pa.y, nv.y);
            fma2(mac[2][0], pc.x, nv.x); fma2(mac[2][1], pc.x, nv.y);
            fma2(mac[3][0], pc.y, nv.x); fma2(mac[3][1], pc.y, nv.y);
        }
        if (nxt < B_NODES) {          // G2: next SECOND half -> slot sF
            __syncwarp();
            k2_half(HBa + sF * NB_HALF * 4, nbr + (size_t)nxt * 4096 + 16 * 128, lane);
            CP_COMMIT();
        }
#pragma unroll 4
        for (int k = 16; k < 32; k++) {
            ulonglong2 pa = *(const ulonglong2*)&pb[k * 8];
            ulonglong2 pc = *(const ulonglong2*)&pb[k * 8 + 4];
            ulonglong2 nv = *(const ulonglong2*)&nbS[(k - 16) * 132 + 4 * lane];
            fma2(mac[0][0], pa.x, nv.x); fma2(mac[0][1], pa.x, nv.y);
            fma2(mac[1][0], pa.y, nv.x); fma2(mac[1][1], pa.y, nv.y);
            fma2(mac[2][0], pc.x, nv.x); fma2(mac[2][1], pc.x, nv.y);
            fma2(mac[3][0], pc.y, nv.x); fma2(mac[3][1], pc.y, nv.y);
        }
        if (nxt2 < B_NODES) {         // G3: next2 FIRST half -> slot sS
            __syncwarp();
            k2_half(HBa + sS * NB_HALF * 4, nbr + (size_t)nxt2 * 4096, lane);
            CP_COMMIT();
        }

        size_t mb = (size_t)node * 528;
#pragma unroll
        for (int h = 0; h < 4; h++) {
            float2 u = unpack2(mac[h][0]), v = unpack2(mac[h][1]);
            *(float4*)&g_m[mb + h * 132 + 4 * lane] = make_float4(u.x, u.y, v.x, v.y);
        }

        node = nxt;
        it3 = (it3 == 2) ? 0 : it3 + 1;
    }
}

// =====================================================================
// Kernel 35 (fused back-end, sequential phases, ALL 8 warps per phase):
//   per 32-node tile: phase V: v = m@Wv + bv -> vt (SMEM);
//                     phase O: out = relu(self + vt@wo + bo)
//   m tile single-buffered; next tile's cp.async issued after phase V
//   (ms dead) and overlapped by phase O; waited at loop top.
// =====================================================================
#define NT35 1024
#define K35_WV 0          // Wv [128][132]  (wkv[:,128:256], padded)
#define K35_WO 16896      // wo  [128][128]
#define K35_MS 33280      // m tile [32 nodes][528]
#define K35_VT 50176      // vt [32][132]
#define K35_BV 54400      // 128
#define K35_BO 54528      // 128
#define K35_SMEMF 54656   // 218624 bytes

__global__ void __launch_bounds__(256, 1) k35(
    const float* __restrict__ wkv, const float* __restrict__ bkv,
    const float* __restrict__ wo, const float* __restrict__ bo,
    float* __restrict__ out)
{
    extern __shared__ float s5[];
    uint32_t sb = smem_u32(s5);
    int t = threadIdx.x;

    for (int i = t * 4; i < 16384; i += 1024) {       // Wv[j][c] padded to 132
        int j = i >> 7, cc = i & 127;
        *(float4*)&s5[K35_WV + j * 132 + cc] = *(const float4*)&wkv[j * 256 + 128 + cc];
    }
    for (int i = t * 4; i < 16384; i += 1024)
        *(float4*)&s5[K35_WO + i] = *(const float4*)&wo[i];
    if (t < 32) *(float4*)&s5[K35_BV + t * 4] = *(const float4*)&bkv[128 + t * 4];
    else if (t < 64) *(float4*)&s5[K35_BO + (t - 32) * 4] = *(const float4*)&bo[(t - 32) * 4];

    const int G = gridDim.x;
    int c = blockIdx.x;
    if (c < NT35) {   // prologue: m[c] -> ms (g_m tile is contiguous, stride matches)
        const float* src = g_m + (size_t)c * 16896;
        uint32_t dst = sb + K35_MS * 4;
        for (int i = t; i < 4224; i += 256) cp16(dst + i * 16, src + i * 4);
        CP_COMMIT();
    }

    int g0 = (t >> 5) * 4, c0 = (t & 31) * 4, h = (t & 31) >> 3;   // V-phase map
    int rb = (t >> 5) * 4, jb = (t & 31) * 4;                      // O-phase map
    float4 bv4 = make_float4(0.f, 0.f, 0.f, 0.f), bo4 = bv4;

    while (c < NT35) {
        int cn = c + G;
        CP_WAIT0();
        __syncthreads();   // m[c] ready; weights ready; prev vt reads done

        // ---- phase V: vt[g][c] = bv[c] + sum_j m[g][h(c)][j] * Wv[j][c] ----
        bv4 = *(float4*)&s5[K35_BV + c0];
        {
            ull acc[4][2];
#pragma unroll
            for (int gg = 0; gg < 4; gg++) {
                acc[gg][0] = pack2(bv4.x, bv4.y);
                acc[gg][1] = pack2(bv4.z, bv4.w);
            }
#pragma unroll 4
            for (int j = 0; j < 128; j++) {
                ulonglong2 w2 = *(const ulonglong2*)&s5[K35_WV + j * 132 + c0];
#pragma unroll
                for (int gg = 0; gg < 4; gg++) {
                    float mv = s5[K35_MS + (g0 + gg) * 528 + h * 132 + j];
                    ull mp = pack2(mv, mv);
                    fma2(acc[gg][0], mp, w2.x);
                    fma2(acc[gg][1], mp, w2.y);
                }
            }
#pragma unroll
            for (int gg = 0; gg < 4; gg++) {
                float2 u = unpack2(acc[gg][0]), v = unpack2(acc[gg][1]);
                *(float4*)&s5[K35_VT + (g0 + gg) * 132 + c0] = make_float4(u.x, u.y, v.x, v.y);
            }
        }
        __syncthreads();   // ms dead, vt ready

        if (cn < NT35) {   // prefetch next m tile (overlapped by phase O)
            const float* src = g_m + (size_t)cn * 16896;
            uint32_t dst = sb + K35_MS * 4;
            for (int i = t; i < 4224; i += 256) cp16(dst + i * 16, src + i * 4);
            CP_COMMIT();
        }

        // ---- phase O: out = relu(self + vt@wo + bo) ----
        bo4 = *(float4*)&s5[K35_BO + jb];
        {
            ull acc[4][2];
#pragma unroll
            for (int rr = 0; rr < 4; rr++) {
                acc[rr][0] = pack2(bo4.x, bo4.y);
                acc[rr][1] = pack2(bo4.z, bo4.w);
            }
#pragma unroll 4
            for (int d = 0; d < 128; d += 2) {
                ulonglong2 w0 = *(ulonglong2*)&s5[K35_WO + d * 128 + jb];
                ulonglong2 w1 = *(ulonglong2*)&s5[K35_WO + (d + 1) * 128 + jb];
#pragma unroll
                for (int rr = 0; rr < 4; rr++) {
                    float2 vv = *(const float2*)&s5[K35_VT + (rb + rr) * 132 + d];
                    ull a0 = pack2(vv.x, vv.x), a1 = pack2(vv.y, vv.y);
                    fma2(acc[rr][0], a0, w0.x); fma2(acc[rr][1], a0, w0.y);
                    fma2(acc[rr][0], a1, w1.x); fma2(acc[rr][1], a1, w1.y);
                }
            }
            size_t row0 = (size_t)c * 32;
#pragma unroll
            for (int rr = 0; rr < 4; rr++) {
                size_t r = row0 + rb + rr;
                float4 sv = *(const float4*)&g_self[r * 128 + jb];
                float2 u = unpack2(acc[rr][0]), v = unpack2(acc[rr][1]);
                float4 o = make_float4(fmaxf(u.x + sv.x, 0.f), fmaxf(u.y + sv.y, 0.f),
                                       fmaxf(v.x + sv.z, 0.f), fmaxf(v.y + sv.w, 0.f));
                *(float4*)&out[r * 128 + jb] = o;
            }
        }
        c = cn;
    }
}

// =====================================================================
// Launch
// =====================================================================
#define K1Z_SMEM (K1Z_SMEMF * 4)                                       // 216576
#define K2_SMEM  (K2_SMEMF * 4)                                        // 227328
#define K35_SMEM (K35_SMEMF * 4)                                       // 218624

extern "C" void kernel_launch(void* const* d_in, const int* in_sizes, int n_in,
                              void* d_out, int out_size)
{
    const float* src   = (const float*)d_in[0];
    const float* nbr   = (const float*)d_in[1];
    const float* wq    = (const float*)d_in[2];
    const float* bq    = (const float*)d_in[3];
    const float* wkv   = (const float*)d_in[4];
    const float* bkv   = (const float*)d_in[5];
    const float* wo    = (const float*)d_in[6];
    const float* bo    = (const float*)d_in[7];
    const float* wself = (const float*)d_in[8];
    float* out = (float*)d_out;

    cudaFuncSetAttribute(k1z,     cudaFuncAttributeMaxDynamicSharedMemorySize, K1Z_SMEM);
    cudaFuncSetAttribute(k2_attn, cudaFuncAttributeMaxDynamicSharedMemorySize, K2_SMEM);
    cudaFuncSetAttribute(k35,     cudaFuncAttributeMaxDynamicSharedMemorySize, K35_SMEM);

    int dev = 0;
    cudaGetDevice(&dev);
    int nsm = 148;
    cudaDeviceGetAttribute(&nsm, cudaDevAttrMultiProcessorCount, dev);

    k1z<<<nsm, 256, K1Z_SMEM>>>(src, wq, bq, wself, wkv);
    k2_attn<<<nsm, 256, K2_SMEM>>>(nbr);
    k35<<<nsm, 256, K35_SMEM>>>(wkv, bkv, wo, bo, out);
}